// round 1
// baseline (speedup 1.0000x reference)
#include <cuda_runtime.h>
#include <math.h>

#define BB 4
#define TT 512
#define SS 1536           // S = 3*T
#define SDIM 64
#define ADIM 32
#define HDIM 512
#define NH 8
#define DH 64
#define NBLK 6
#define DFF 2048
#define MROWS (BB*SS)     // 6144

#define TM 64
#define TN 64
#define TK 16

enum { EP_BIAS = 0, EP_BIAS_RES = 1, EP_BIAS_GELU = 2 };

// ---------------- scratch (static device globals; no runtime allocs) ----------
__device__ float g_h   [MROWS * HDIM];
__device__ float g_q   [MROWS * HDIM];
__device__ float g_k   [MROWS * HDIM];
__device__ float g_v   [MROWS * HDIM];
__device__ float g_ctx [MROWS * HDIM];
__device__ float g_xa  [MROWS * HDIM];
__device__ float g_ln1 [MROWS * HDIM];
__device__ float g_pre2[MROWS * HDIM];
__device__ float g_mlp [MROWS * DFF];
__device__ float g_sc  [(size_t)BB * NH * SS * SS];   // 302 MB scores

// ---------------- reductions ----------------
__device__ __forceinline__ float blockReduceSum(float v, float* sm) {
    int lane = threadIdx.x & 31, wid = threadIdx.x >> 5;
    #pragma unroll
    for (int o = 16; o; o >>= 1) v += __shfl_down_sync(0xffffffffu, v, o);
    if (lane == 0) sm[wid] = v;
    __syncthreads();
    float r = 0.f;
    if (wid == 0) {
        r = (lane < 8) ? sm[lane] : 0.f;
        #pragma unroll
        for (int o = 4; o; o >>= 1) r += __shfl_down_sync(0xffffffffu, r, o);
        if (lane == 0) sm[0] = r;
    }
    __syncthreads();
    r = sm[0];
    __syncthreads();
    return r;
}

__device__ __forceinline__ float blockReduceMax(float v, float* sm) {
    int lane = threadIdx.x & 31, wid = threadIdx.x >> 5;
    #pragma unroll
    for (int o = 16; o; o >>= 1) v = fmaxf(v, __shfl_down_sync(0xffffffffu, v, o));
    if (lane == 0) sm[wid] = v;
    __syncthreads();
    float r = -1e30f;
    if (wid == 0) {
        r = (lane < 8) ? sm[lane] : -1e30f;
        #pragma unroll
        for (int o = 4; o; o >>= 1) r = fmaxf(r, __shfl_down_sync(0xffffffffu, r, o));
        if (lane == 0) sm[0] = r;
    }
    __syncthreads();
    r = sm[0];
    __syncthreads();
    return r;
}

// ---------------- embedding + eLN (one block per sequence row) ----------------
__global__ __launch_bounds__(256) void embed_kernel(
    const int* __restrict__ timesteps, const float* __restrict__ s0,
    const float* __restrict__ s1, const float* __restrict__ act,
    const float* __restrict__ temb,
    const float* __restrict__ Ws, const float* __restrict__ bs,
    const float* __restrict__ Wa, const float* __restrict__ ba,
    const float* __restrict__ eg, const float* __restrict__ eb,
    float* __restrict__ out)
{
    int s = blockIdx.x;
    int b = s / SS, sr = s % SS;
    int t = sr / 3, r = sr % 3;

    __shared__ float sIn[SDIM];
    __shared__ float red[32];

    const float* inp; const float* W; const float* bias; int Kin;
    if (r == 0)      { inp = s0  + (size_t)(b*TT + t)*SDIM; W = Ws; bias = bs; Kin = SDIM; }
    else if (r == 1) { inp = s1  + (size_t)(b*TT + t)*SDIM; W = Ws; bias = bs; Kin = SDIM; }
    else             { inp = act + (size_t)(b*TT + t)*ADIM; W = Wa; bias = ba; Kin = ADIM; }

    int tid = threadIdx.x;
    if (tid < Kin) sIn[tid] = inp[tid];
    __syncthreads();

    int tsv = timesteps[b*TT + t];
    const float* te = temb + (size_t)tsv * HDIM;

    float v0, v1;
    {
        int c = tid;
        float a = bias[c] + te[c];
        for (int k = 0; k < Kin; k++) a = fmaf(sIn[k], W[(size_t)k*HDIM + c], a);
        v0 = a;
        c = tid + 256;
        a = bias[c] + te[c];
        for (int k = 0; k < Kin; k++) a = fmaf(sIn[k], W[(size_t)k*HDIM + c], a);
        v1 = a;
    }
    float sum = blockReduceSum(v0 + v1, red);
    float m = sum * (1.0f / HDIM);
    float d0 = v0 - m, d1 = v1 - m;
    float ssq = blockReduceSum(d0*d0 + d1*d1, red);
    float rstd = rsqrtf(ssq * (1.0f / HDIM) + 1e-5f);
    out[(size_t)s*HDIM + tid      ] = d0 * rstd * eg[tid]       + eb[tid];
    out[(size_t)s*HDIM + tid + 256] = d1 * rstd * eg[tid + 256] + eb[tid + 256];
}

// ---------------- generic tiled SGEMM with fused epilogue ----------------
// C[M,N] = A[M,K] @ W[K,N] (+bias, +res, gelu). All dims multiples of tile sizes.
__global__ __launch_bounds__(256) void gemm_kernel(
    const float* __restrict__ A, const float* __restrict__ W,
    const float* __restrict__ bias, const float* __restrict__ res,
    float* __restrict__ C, int M, int N, int K, int ep)
{
    __shared__ float As[TK][TM];
    __shared__ float Bs[TK][TN];
    int tid = threadIdx.x;
    int tx = tid % 16, ty = tid / 16;
    int m0 = blockIdx.y * TM, n0 = blockIdx.x * TN;

    int ar = tid / 4, ac = (tid % 4) * 4;     // A tile loader: row 0..63, col 0/4/8/12
    int br = tid / 16, bc = (tid % 16) * 4;   // B tile loader: row 0..15, col 0..60

    float acc[4][4] = {};
    for (int k0 = 0; k0 < K; k0 += TK) {
        float4 av = *(const float4*)(A + (size_t)(m0 + ar)*K + k0 + ac);
        As[ac+0][ar] = av.x; As[ac+1][ar] = av.y; As[ac+2][ar] = av.z; As[ac+3][ar] = av.w;
        *(float4*)&Bs[br][bc] = *(const float4*)(W + (size_t)(k0 + br)*N + n0 + bc);
        __syncthreads();
        #pragma unroll
        for (int kk = 0; kk < TK; kk++) {
            float a[4], bv[4];
            #pragma unroll
            for (int i = 0; i < 4; i++) a[i] = As[kk][ty*4 + i];
            #pragma unroll
            for (int j = 0; j < 4; j++) bv[j] = Bs[kk][tx*4 + j];
            #pragma unroll
            for (int i = 0; i < 4; i++)
                #pragma unroll
                for (int j = 0; j < 4; j++)
                    acc[i][j] = fmaf(a[i], bv[j], acc[i][j]);
        }
        __syncthreads();
    }
    #pragma unroll
    for (int i = 0; i < 4; i++) {
        int row = m0 + ty*4 + i;
        #pragma unroll
        for (int j = 0; j < 4; j++) {
            int col = n0 + tx*4 + j;
            float v = acc[i][j] + bias[col];
            if (ep == EP_BIAS_RES)       v += res[(size_t)row*N + col];
            else if (ep == EP_BIAS_GELU) v = 0.5f * v * (1.0f + erff(v * 0.70710678118654752f));
            C[(size_t)row*N + col] = v;
        }
    }
}

// ---------------- attention scores: Q @ K^T (lower-triangle tiles only) -------
__global__ __launch_bounds__(256) void scores_kernel(
    const float* __restrict__ q, const float* __restrict__ k, float* __restrict__ sc)
{
    int jt = blockIdx.x, it = blockIdx.y;
    if (jt > it) return;
    int bh = blockIdx.z, b = bh >> 3, h = bh & 7;
    const float* qb = q + (size_t)b*SS*HDIM + h*DH;
    const float* kb = k + (size_t)b*SS*HDIM + h*DH;
    float* cb = sc + (size_t)bh * SS * SS;
    int i0 = it * TM, j0 = jt * TN;

    __shared__ float Qs[TK][TM];
    __shared__ float Ks[TK][TN];
    int tid = threadIdx.x;
    int tx = tid % 16, ty = tid / 16;
    int ar = tid / 4, ac = (tid % 4) * 4;

    float acc[4][4] = {};
    for (int k0 = 0; k0 < DH; k0 += TK) {
        float4 av = *(const float4*)(qb + (size_t)(i0 + ar)*HDIM + k0 + ac);
        Qs[ac+0][ar] = av.x; Qs[ac+1][ar] = av.y; Qs[ac+2][ar] = av.z; Qs[ac+3][ar] = av.w;
        float4 bv = *(const float4*)(kb + (size_t)(j0 + ar)*HDIM + k0 + ac);
        Ks[ac+0][ar] = bv.x; Ks[ac+1][ar] = bv.y; Ks[ac+2][ar] = bv.z; Ks[ac+3][ar] = bv.w;
        __syncthreads();
        #pragma unroll
        for (int kk = 0; kk < TK; kk++) {
            float a[4], bv2[4];
            #pragma unroll
            for (int i = 0; i < 4; i++) a[i] = Qs[kk][ty*4 + i];
            #pragma unroll
            for (int j = 0; j < 4; j++) bv2[j] = Ks[kk][tx*4 + j];
            #pragma unroll
            for (int i = 0; i < 4; i++)
                #pragma unroll
                for (int j = 0; j < 4; j++)
                    acc[i][j] = fmaf(a[i], bv2[j], acc[i][j]);
        }
        __syncthreads();
    }
    const float scale = 0.125f; // 1/sqrt(64)
    #pragma unroll
    for (int i = 0; i < 4; i++) {
        int row = i0 + ty*4 + i;
        #pragma unroll
        for (int j = 0; j < 4; j++)
            cb[(size_t)row*SS + j0 + tx*4 + j] = acc[i][j] * scale;
    }
}

// ---------------- causal row softmax (zero-fill to tile boundary) -------------
__global__ __launch_bounds__(256) void softmax_kernel(float* __restrict__ sc)
{
    size_t rid = blockIdx.x;            // bh*S + i
    int i = (int)(rid % SS);
    float* row = sc + rid * (size_t)SS;
    int n = i + 1;
    int end = ((i / TM) + 1) * TM;      // ctx GEMM reads j < tile_end
    __shared__ float red[32];

    float mx = -1e30f;
    for (int j = threadIdx.x; j < n; j += 256) mx = fmaxf(mx, row[j]);
    mx = blockReduceMax(mx, red);

    float sum = 0.f;
    for (int j = threadIdx.x; j < n; j += 256) {
        float e = __expf(row[j] - mx);
        row[j] = e;
        sum += e;
    }
    sum = blockReduceSum(sum, red);
    float inv = 1.0f / sum;
    for (int j = threadIdx.x; j < n; j += 256) row[j] *= inv;
    for (int j = n + threadIdx.x; j < end; j += 256) row[j] = 0.f;
}

// ---------------- ctx = attn @ V (K-limit per row tile) -----------------------
__global__ __launch_bounds__(256) void ctx_kernel(
    const float* __restrict__ at, const float* __restrict__ v, float* __restrict__ ctx)
{
    int it = blockIdx.x, bh = blockIdx.y, b = bh >> 3, h = bh & 7;
    const float* ab = at + (size_t)bh * SS * SS;
    const float* vb = v   + (size_t)b*SS*HDIM + h*DH;
    float* cb       = ctx + (size_t)b*SS*HDIM + h*DH;
    int i0 = it * TM;
    int kmax = i0 + TM;   // causal: rows in this tile attend to j < i0+64

    __shared__ float As[TK][TM];
    __shared__ float Bs[TK][TN];
    int tid = threadIdx.x;
    int tx = tid % 16, ty = tid / 16;
    int ar = tid / 4, ac = (tid % 4) * 4;
    int br = tid / 16, bc = (tid % 16) * 4;

    float acc[4][4] = {};
    for (int k0 = 0; k0 < kmax; k0 += TK) {
        float4 av = *(const float4*)(ab + (size_t)(i0 + ar)*SS + k0 + ac);
        As[ac+0][ar] = av.x; As[ac+1][ar] = av.y; As[ac+2][ar] = av.z; As[ac+3][ar] = av.w;
        *(float4*)&Bs[br][bc] = *(const float4*)(vb + (size_t)(k0 + br)*HDIM + bc);
        __syncthreads();
        #pragma unroll
        for (int kk = 0; kk < TK; kk++) {
            float a[4], bv2[4];
            #pragma unroll
            for (int i = 0; i < 4; i++) a[i] = As[kk][ty*4 + i];
            #pragma unroll
            for (int j = 0; j < 4; j++) bv2[j] = Bs[kk][tx*4 + j];
            #pragma unroll
            for (int i = 0; i < 4; i++)
                #pragma unroll
                for (int j = 0; j < 4; j++)
                    acc[i][j] = fmaf(a[i], bv2[j], acc[i][j]);
        }
        __syncthreads();
    }
    #pragma unroll
    for (int i = 0; i < 4; i++) {
        int row = i0 + ty*4 + i;
        #pragma unroll
        for (int j = 0; j < 4; j++)
            cb[(size_t)row*HDIM + tx*4 + j] = acc[i][j];
    }
}

// ---------------- plain layernorm over HDIM ----------------
__global__ __launch_bounds__(256) void ln_kernel(
    const float* __restrict__ x, const float* __restrict__ g,
    const float* __restrict__ b, float* __restrict__ out)
{
    int row = blockIdx.x;
    __shared__ float red[32];
    int tid = threadIdx.x;
    float v0 = x[(size_t)row*HDIM + tid];
    float v1 = x[(size_t)row*HDIM + tid + 256];
    float sum = blockReduceSum(v0 + v1, red);
    float m = sum * (1.0f / HDIM);
    float d0 = v0 - m, d1 = v1 - m;
    float ssq = blockReduceSum(d0*d0 + d1*d1, red);
    float rstd = rsqrtf(ssq * (1.0f / HDIM) + 1e-5f);
    out[(size_t)row*HDIM + tid      ] = d0 * rstd * g[tid]       + b[tid];
    out[(size_t)row*HDIM + tid + 256] = d1 * rstd * g[tid + 256] + b[tid + 256];
}

// ---------------- final projection: out = h[:, :, 1] @ Wp + bp ----------------
__global__ __launch_bounds__(256) void final_kernel(
    const float* __restrict__ h, const float* __restrict__ Wp,
    const float* __restrict__ bp, float* __restrict__ out)
{
    int bt = blockIdx.x;                 // b*T + t
    int b = bt / TT, t = bt % TT;
    const float* row = h + ((size_t)b*SS + 3*t + 1) * HDIM;
    __shared__ float sRow[HDIM];
    __shared__ float part[8][ADIM];
    int tid = threadIdx.x;
    sRow[tid] = row[tid];
    sRow[tid + 256] = row[tid + 256];
    __syncthreads();
    int c = tid & 31, g = tid >> 5;      // 8 k-groups x 32 cols
    float a = 0.f;
    for (int k = g*64; k < (g+1)*64; k++) a = fmaf(sRow[k], Wp[(size_t)k*ADIM + c], a);
    part[g][c] = a;
    __syncthreads();
    if (tid < ADIM) {
        float s = bp[tid];
        #pragma unroll
        for (int g2 = 0; g2 < 8; g2++) s += part[g2][tid];
        out[(size_t)bt*ADIM + tid] = s;
    }
}

// ---------------- driver ----------------
extern "C" void kernel_launch(void* const* d_in, const int* in_sizes, int n_in,
                              void* d_out, int out_size)
{
    const int*   timesteps = (const int*)  d_in[0];
    const float* state_0   = (const float*)d_in[1];
    const float* state_1   = (const float*)d_in[2];
    const float* actions   = (const float*)d_in[3];
    const float* time_emb  = (const float*)d_in[4];
    const float* Ws  = (const float*)d_in[5];
    const float* bs  = (const float*)d_in[6];
    const float* Wa  = (const float*)d_in[7];
    const float* ba  = (const float*)d_in[8];
    const float* Wq  = (const float*)d_in[9];
    const float* bq  = (const float*)d_in[10];
    const float* Wk  = (const float*)d_in[11];
    const float* bk  = (const float*)d_in[12];
    const float* Wv  = (const float*)d_in[13];
    const float* bv  = (const float*)d_in[14];
    const float* Wo  = (const float*)d_in[15];
    const float* bo  = (const float*)d_in[16];
    const float* W1  = (const float*)d_in[17];
    const float* b1  = (const float*)d_in[18];
    const float* W2  = (const float*)d_in[19];
    const float* b2  = (const float*)d_in[20];
    const float* ln1_g = (const float*)d_in[21];
    const float* ln1_b = (const float*)d_in[22];
    const float* ln2_g = (const float*)d_in[23];
    const float* ln2_b = (const float*)d_in[24];
    const float* eln_g = (const float*)d_in[25];
    const float* eln_b = (const float*)d_in[26];
    const float* Wp  = (const float*)d_in[27];
    const float* bp  = (const float*)d_in[28];

    float *h, *q, *k, *v, *ctx, *xa, *ln1o, *pre2, *mlp, *sc;
    cudaGetSymbolAddress((void**)&h,    g_h);
    cudaGetSymbolAddress((void**)&q,    g_q);
    cudaGetSymbolAddress((void**)&k,    g_k);
    cudaGetSymbolAddress((void**)&v,    g_v);
    cudaGetSymbolAddress((void**)&ctx,  g_ctx);
    cudaGetSymbolAddress((void**)&xa,   g_xa);
    cudaGetSymbolAddress((void**)&ln1o, g_ln1);
    cudaGetSymbolAddress((void**)&pre2, g_pre2);
    cudaGetSymbolAddress((void**)&mlp,  g_mlp);
    cudaGetSymbolAddress((void**)&sc,   g_sc);

    embed_kernel<<<BB*SS, 256>>>(timesteps, state_0, state_1, actions, time_emb,
                                 Ws, bs, Wa, ba, eln_g, eln_b, h);

    dim3 gH(HDIM/TN, MROWS/TM);   // (8, 96)
    dim3 gF(DFF /TN, MROWS/TM);   // (32, 96)
    dim3 gS(SS/TM, SS/TM, BB*NH); // (24, 24, 32)
    dim3 gC(SS/TM, BB*NH);        // (24, 32)

    for (int blk = 0; blk < NBLK; blk++) {
        const float* Wq_ = Wq + (size_t)blk*HDIM*HDIM;
        const float* Wk_ = Wk + (size_t)blk*HDIM*HDIM;
        const float* Wv_ = Wv + (size_t)blk*HDIM*HDIM;
        const float* Wo_ = Wo + (size_t)blk*HDIM*HDIM;
        const float* W1_ = W1 + (size_t)blk*HDIM*DFF;
        const float* W2_ = W2 + (size_t)blk*DFF*HDIM;
        const float* bq_ = bq + (size_t)blk*HDIM;
        const float* bk_ = bk + (size_t)blk*HDIM;
        const float* bv_ = bv + (size_t)blk*HDIM;
        const float* bo_ = bo + (size_t)blk*HDIM;
        const float* b1_ = b1 + (size_t)blk*DFF;
        const float* b2_ = b2 + (size_t)blk*HDIM;
        const float* g1_ = ln1_g + (size_t)blk*HDIM;
        const float* e1_ = ln1_b + (size_t)blk*HDIM;
        const float* g2_ = ln2_g + (size_t)blk*HDIM;
        const float* e2_ = ln2_b + (size_t)blk*HDIM;

        gemm_kernel<<<gH, 256>>>(h, Wq_, bq_, nullptr, q, MROWS, HDIM, HDIM, EP_BIAS);
        gemm_kernel<<<gH, 256>>>(h, Wk_, bk_, nullptr, k, MROWS, HDIM, HDIM, EP_BIAS);
        gemm_kernel<<<gH, 256>>>(h, Wv_, bv_, nullptr, v, MROWS, HDIM, HDIM, EP_BIAS);

        scores_kernel <<<gS, 256>>>(q, k, sc);
        softmax_kernel<<<BB*NH*SS, 256>>>(sc);
        ctx_kernel    <<<gC, 256>>>(sc, v, ctx);

        gemm_kernel<<<gH, 256>>>(ctx, Wo_, bo_, h, xa, MROWS, HDIM, HDIM, EP_BIAS_RES);
        ln_kernel  <<<MROWS, 256>>>(xa, g1_, e1_, ln1o);
        gemm_kernel<<<gF, 256>>>(ln1o, W1_, b1_, nullptr, mlp, MROWS, DFF, HDIM, EP_BIAS_GELU);
        gemm_kernel<<<gH, 256>>>(mlp, W2_, b2_, ln1o, pre2, MROWS, HDIM, DFF, EP_BIAS_RES);
        ln_kernel  <<<MROWS, 256>>>(pre2, g2_, e2_, h);
    }

    final_kernel<<<BB*TT, 256>>>(h, Wp, bp, (float*)d_out);
}